// round 8
// baseline (speedup 1.0000x reference)
#include <cuda_runtime.h>

// Problem constants (fixed shapes from reference)
#define BB 4
#define NN 19
#define HH 512
#define WW 512
#define HWc (HH * WW)          // 262144
#define CC 57
#define PAIRS (BB * NN)        // 76
#define TILES 32
#define NBLOCKS (PAIRS * TILES)             // 2432 worker CTAs (+1 watcher)
#define THREADS 256
#define V_PER_TILE (HWc / 4 / TILES)        // 2048 float4 per tile
#define V_PER_THREAD (V_PER_TILE / THREADS) // 8 float4 per thread per plane

// Per-pair accumulators. Zero at module load; the watcher resets them to zero
// after consuming -> state identical on every graph replay.
__device__ float g_bce[PAIRS];
__device__ float g_l1x[PAIRS];
__device__ float g_l1y[PAIRS];
__device__ float g_cnt[PAIRS];
__device__ unsigned int g_count = 0;

__global__ __launch_bounds__(THREADS, 5) void hm_main_kernel(
    const float* __restrict__ fm, const float* __restrict__ lms,
    float* __restrict__ out)
{
    // ---------------- watcher CTA: finalize ----------------
    if (blockIdx.x == NBLOCKS) {
        const int tid = threadIdx.x;
        if (tid == 0) {
            volatile unsigned int* vc = &g_count;
            while (*vc != (unsigned int)NBLOCKS) __nanosleep(200);
        }
        __syncthreads();
        __threadfence();   // acquire: accumulator REDs visible after count

        float t = 0.0f;
        if (tid < PAIRS) {
            const float vb = __ldcg(&g_bce[tid]);
            const float vx = __ldcg(&g_l1x[tid]);
            const float vy = __ldcg(&g_l1y[tid]);
            const float vn = __ldcg(&g_cnt[tid]);
            t = 2.0f * vb * (1.0f / (float)HWc) + (vx + vy) / vn;
        }
        #pragma unroll
        for (int o = 16; o > 0; o >>= 1)
            t += __shfl_down_sync(0xFFFFFFFFu, t, o);

        __shared__ float s[8];
        const int warp = tid >> 5, lane = tid & 31;
        if (lane == 0) s[warp] = t;
        __syncthreads();
        if (tid == 0) {
            float sum = 0.0f;
            #pragma unroll
            for (int i = 0; i < 8; i++) sum += s[i];
            out[0] = sum / (float)PAIRS;
        }
        // reset state for the next graph replay (end state == initial state)
        if (tid < PAIRS) {
            g_bce[tid] = 0.0f; g_l1x[tid] = 0.0f;
            g_l1y[tid] = 0.0f; g_cnt[tid] = 0.0f;
        }
        if (tid == 0) g_count = 0;
        return;
    }

    // ---------------- worker CTAs ----------------
    const int pair = blockIdx.x / TILES;
    const int tile = blockIdx.x % TILES;
    const int b = pair / NN;
    const int n = pair % NN;

    // landmark -> integer center (matches (lm * [H,W]).astype(int32) truncation)
    const float lx = lms[pair * 2 + 0];
    const float ly = lms[pair * 2 + 1];
    const int x = (int)(lx * (float)HH);
    const int y = (int)(ly * (float)WW);

    const size_t base = ((size_t)(b * CC + n)) * (size_t)HWc;
    const float4* __restrict__ pL = (const float4*)(fm + base);
    const float4* __restrict__ pX = (const float4*)(fm + base + (size_t)NN * HWc);
    const float4* __restrict__ pY = (const float4*)(fm + base + (size_t)(2 * NN) * HWc);

    float bce_lin = 0.0f;   // Sum of (l + |l|)  == 2*max(l,0)
    float bce_log = 0.0f;   // Sum of log(1+exp(-|l|)) via log-of-products
    float bce_sub = 0.0f;   // Sum of l over heat==1 pixels
    float l1x = 0.0f, l1y = 0.0f;
    int cnt = 0;

    const int vbase = tile * V_PER_TILE + threadIdx.x;

    // Front-batch ALL 8 independent LDG.128 before any compute (MLP_p1 = 8).
    float4 bufA[4], bufB[4];
    #pragma unroll
    for (int j = 0; j < 4; j++) bufA[j] = __ldcs(pL + vbase + j * THREADS);
    #pragma unroll
    for (int j = 0; j < 4; j++) bufB[j] = __ldcs(pL + vbase + (4 + j) * THREADS);

    #pragma unroll
    for (int k = 0; k < V_PER_THREAD; k++) {
        const float4 L = (k < 4) ? bufA[k] : bufB[k - 4];
        const int v = vbase + k * THREADS;

        const int h = v >> 7;           // v / 128 (128 float4 per row)
        const int w = (v & 127) << 2;   // starting column of this float4

        const int di = h - x;
        const int di2 = di * di;
        const int rem = 1600 - di2;     // dj^2 budget for this row

        float Lv[4] = {L.x, L.y, L.z, L.w};

        // softplus sum via log of product: 4 parallel EX2 + product tree + 1 LG2
        {
            const float a0 = fabsf(Lv[0]), a1 = fabsf(Lv[1]);
            const float a2 = fabsf(Lv[2]), a3 = fabsf(Lv[3]);
            bce_lin += (Lv[0] + a0) + (Lv[1] + a1) + (Lv[2] + a2) + (Lv[3] + a3);
            const float e0 = 1.0f + __expf(-a0);
            const float e1 = 1.0f + __expf(-a1);
            const float e2 = 1.0f + __expf(-a2);
            const float e3 = 1.0f + __expf(-a3);
            bce_log += __logf((e0 * e1) * (e2 * e3));
        }

        // Can any of the 4 lanes be inside the disk? (exact test)
        const int dj0 = w - y;               // lane j has dj = dj0 + j
        const int djc = (dj0 > 0) ? dj0 : ((dj0 + 3 < 0) ? -(dj0 + 3) : 0);
        const bool need = (rem >= 0) && (djc * djc <= rem);

        if (need) {
            // PX/PY loaded only inside (or at the fringe of) the disk: ~2% of px
            const float4 PX = __ldcs(pX + v);
            const float4 PY = __ldcs(pY + v);
            const float offx = -(float)di * (1.0f / 40.0f);
            float PXv[4] = {PX.x, PX.y, PX.z, PX.w};
            float PYv[4] = {PY.x, PY.y, PY.z, PY.w};
            #pragma unroll
            for (int j = 0; j < 4; j++) {
                const int dj = dj0 + j;
                if (dj * dj <= rem) {        // heat == 1
                    bce_sub += Lv[j];
                    const float offy = -(float)dj * (1.0f / 40.0f);
                    l1x += fabsf(PXv[j] - offx);
                    l1y += fabsf(PYv[j] - offy);
                    cnt++;
                }
            }
        }
    }

    // bce = 0.5*sum(l+|l|) + sum(softplus) - sum_heat(l)
    float bce = fmaf(0.5f, bce_lin, bce_log) - bce_sub;

    // block reduction: warp shfl, then cross-warp via smem
    float c = (float)cnt;
    #pragma unroll
    for (int o = 16; o > 0; o >>= 1) {
        bce += __shfl_down_sync(0xFFFFFFFFu, bce, o);
        l1x += __shfl_down_sync(0xFFFFFFFFu, l1x, o);
        l1y += __shfl_down_sync(0xFFFFFFFFu, l1y, o);
        c   += __shfl_down_sync(0xFFFFFFFFu, c, o);
    }

    __shared__ float s0[8], s1[8], s2[8], s3[8];
    const int warp = threadIdx.x >> 5;
    const int lane = threadIdx.x & 31;
    if (lane == 0) { s0[warp] = bce; s1[warp] = l1x; s2[warp] = l1y; s3[warp] = c; }
    __syncthreads();
    // warps 1..7 retire here; only thread0 pays the fence.

    if (threadIdx.x == 0) {
        float v0 = 0.f, v1 = 0.f, v2 = 0.f, v3 = 0.f;
        #pragma unroll
        for (int i = 0; i < 8; i++) {
            v0 += s0[i]; v1 += s1[i]; v2 += s2[i]; v3 += s3[i];
        }
        // fire-and-forget REDG accumulation (results unused -> no round trip)
        atomicAdd(&g_bce[pair], v0);
        atomicAdd(&g_l1x[pair], v1);
        atomicAdd(&g_l1y[pair], v2);
        atomicAdd(&g_cnt[pair], v3);
        __threadfence();              // order data REDs before the count RED
        atomicAdd(&g_count, 1u);      // fire-and-forget
    }
}

extern "C" void kernel_launch(void* const* d_in, const int* in_sizes, int n_in,
                              void* d_out, int out_size)
{
    const float* fm  = (const float*)d_in[0];   // feature_maps (4,57,512,512) f32
    const float* lms = (const float*)d_in[1];   // landmarks (4,19,2) f32
    float* out = (float*)d_out;

    hm_main_kernel<<<NBLOCKS + 1, THREADS>>>(fm, lms, out);
}

// round 9
// speedup vs baseline: 1.2303x; 1.2303x over previous
#include <cuda_runtime.h>

// Problem constants (fixed shapes from reference)
#define BB 4
#define NN 19
#define HH 512
#define WW 512
#define HWc (HH * WW)          // 262144
#define CC 57
#define PAIRS (BB * NN)        // 76
#define TILES 32
#define NBLOCKS (PAIRS * TILES)             // 2432 stream CTAs
#define NDISK PAIRS                          // 76 disk CTAs
#define NWORK (NBLOCKS + NDISK)              // 2508 worker CTAs (+1 watcher)
#define THREADS 256
#define V_PER_TILE (HWc / 4 / TILES)        // 2048 float4 per tile
#define V_PER_THREAD (V_PER_TILE / THREADS) // 8 float4 per thread

#define RAD 40
#define BBOX 81                              // 2*RAD+1
#define BBOX2 (BBOX * BBOX)                  // 6561

// Per-pair accumulators. Zero at module load; the watcher resets them to zero
// after consuming -> state identical on every graph replay.
__device__ float g_bce[PAIRS];
__device__ float g_l1x[PAIRS];
__device__ float g_l1y[PAIRS];
__device__ float g_cnt[PAIRS];
__device__ unsigned int g_count = 0;

__global__ __launch_bounds__(THREADS, 6) void hm_main_kernel(
    const float* __restrict__ fm, const float* __restrict__ lms,
    float* __restrict__ out)
{
    const int warp = threadIdx.x >> 5;
    const int lane = threadIdx.x & 31;

    // ---------------- watcher CTA: finalize ----------------
    if (blockIdx.x == NWORK) {
        const int tid = threadIdx.x;
        if (tid == 0) {
            volatile unsigned int* vc = &g_count;
            while (*vc != (unsigned int)NWORK) __nanosleep(200);
        }
        __syncthreads();
        __threadfence();   // acquire: accumulator REDs visible after count

        float t = 0.0f;
        if (tid < PAIRS) {
            const float vb = __ldcg(&g_bce[tid]);
            const float vx = __ldcg(&g_l1x[tid]);
            const float vy = __ldcg(&g_l1y[tid]);
            const float vn = __ldcg(&g_cnt[tid]);
            t = 2.0f * vb * (1.0f / (float)HWc) + (vx + vy) / vn;
        }
        #pragma unroll
        for (int o = 16; o > 0; o >>= 1)
            t += __shfl_down_sync(0xFFFFFFFFu, t, o);

        __shared__ float s[8];
        if (lane == 0) s[warp] = t;
        __syncthreads();
        if (tid == 0) {
            float sum = 0.0f;
            #pragma unroll
            for (int i = 0; i < 8; i++) sum += s[i];
            out[0] = sum / (float)PAIRS;
        }
        // reset state for the next graph replay (end state == initial state)
        if (tid < PAIRS) {
            g_bce[tid] = 0.0f; g_l1x[tid] = 0.0f;
            g_l1y[tid] = 0.0f; g_cnt[tid] = 0.0f;
        }
        if (tid == 0) g_count = 0;
        return;
    }

    // ---------------- disk CTAs: heat-region terms ----------------
    if (blockIdx.x >= NBLOCKS) {
        const int pair = blockIdx.x - NBLOCKS;   // 0..75
        const int b = pair / NN;
        const int n = pair % NN;
        const float lx = lms[pair * 2 + 0];
        const float ly = lms[pair * 2 + 1];
        const int x = (int)(lx * (float)HH);
        const int y = (int)(ly * (float)WW);

        const size_t base = ((size_t)(b * CC + n)) * (size_t)HWc;
        const float* __restrict__ pL = fm + base;
        const float* __restrict__ pX = fm + base + (size_t)NN * HWc;
        const float* __restrict__ pY = fm + base + (size_t)(2 * NN) * HWc;

        float subL = 0.0f, l1x = 0.0f, l1y = 0.0f;
        int cnt = 0;

        for (int idx = threadIdx.x; idx < BBOX2; idx += THREADS) {
            const int r  = idx / BBOX;       // 0..80
            const int cc = idx - r * BBOX;   // 0..80
            const int di = r - RAD;
            const int dj = cc - RAD;
            const int gi = x + di;
            const int gj = y + dj;
            if ((unsigned)gi < HH && (unsigned)gj < WW &&
                di * di + dj * dj <= RAD * RAD) {
                const int off = gi * WW + gj;
                const float l  = __ldg(pL + off);
                const float px = __ldg(pX + off);
                const float py = __ldg(pY + off);
                subL += l;
                l1x += fabsf(px + (float)di * (1.0f / 40.0f));  // |px - (-di/40)|
                l1y += fabsf(py + (float)dj * (1.0f / 40.0f));
                cnt++;
            }
        }

        float c = (float)cnt;
        float nb = -subL;   // contribution to bce: -sum_heat(l)
        #pragma unroll
        for (int o = 16; o > 0; o >>= 1) {
            nb  += __shfl_down_sync(0xFFFFFFFFu, nb, o);
            l1x += __shfl_down_sync(0xFFFFFFFFu, l1x, o);
            l1y += __shfl_down_sync(0xFFFFFFFFu, l1y, o);
            c   += __shfl_down_sync(0xFFFFFFFFu, c, o);
        }
        __shared__ float d0[8], d1[8], d2[8], d3[8];
        if (lane == 0) { d0[warp] = nb; d1[warp] = l1x; d2[warp] = l1y; d3[warp] = c; }
        __syncthreads();
        if (threadIdx.x == 0) {
            float v0 = 0.f, v1 = 0.f, v2 = 0.f, v3 = 0.f;
            #pragma unroll
            for (int i = 0; i < 8; i++) {
                v0 += d0[i]; v1 += d1[i]; v2 += d2[i]; v3 += d3[i];
            }
            atomicAdd(&g_bce[pair], v0);
            atomicAdd(&g_l1x[pair], v1);
            atomicAdd(&g_l1y[pair], v2);
            atomicAdd(&g_cnt[pair], v3);
            __threadfence();
            atomicAdd(&g_count, 1u);
        }
        return;
    }

    // ---------------- stream CTAs: bce hot terms over all logits ----------------
    const int pair = blockIdx.x / TILES;
    const int tile = blockIdx.x % TILES;
    const int b = pair / NN;
    const int n = pair % NN;

    const size_t base = ((size_t)(b * CC + n)) * (size_t)HWc;
    const float4* __restrict__ pL = (const float4*)(fm + base);

    float bce_lin = 0.0f;   // Sum of (l + |l|)  == 2*max(l,0)
    float bce_log = 0.0f;   // Sum of log(1+exp(-|l|)) via log-of-products

    const int vbase = tile * V_PER_TILE + threadIdx.x;

    #pragma unroll
    for (int k = 0; k < V_PER_THREAD; k++) {
        const float4 L = __ldcs(pL + vbase + k * THREADS);

        const float a0 = fabsf(L.x), a1 = fabsf(L.y);
        const float a2 = fabsf(L.z), a3 = fabsf(L.w);
        bce_lin += ((L.x + a0) + (L.y + a1)) + ((L.z + a2) + (L.w + a3));
        const float e0 = 1.0f + __expf(-a0);
        const float e1 = 1.0f + __expf(-a1);
        const float e2 = 1.0f + __expf(-a2);
        const float e3 = 1.0f + __expf(-a3);
        bce_log += __logf((e0 * e1) * (e2 * e3));
    }

    // bce partial = 0.5*sum(l+|l|) + sum(softplus)
    float bce = fmaf(0.5f, bce_lin, bce_log);

    #pragma unroll
    for (int o = 16; o > 0; o >>= 1)
        bce += __shfl_down_sync(0xFFFFFFFFu, bce, o);

    __shared__ float s0[8];
    if (lane == 0) s0[warp] = bce;
    __syncthreads();
    // warps 1..7 retire here; only thread0 pays the fence.

    if (threadIdx.x == 0) {
        float v0 = 0.f;
        #pragma unroll
        for (int i = 0; i < 8; i++) v0 += s0[i];
        atomicAdd(&g_bce[pair], v0);   // fire-and-forget REDG
        __threadfence();               // order data RED before the count RED
        atomicAdd(&g_count, 1u);
    }
}

extern "C" void kernel_launch(void* const* d_in, const int* in_sizes, int n_in,
                              void* d_out, int out_size)
{
    const float* fm  = (const float*)d_in[0];   // feature_maps (4,57,512,512) f32
    const float* lms = (const float*)d_in[1];   // landmarks (4,19,2) f32
    float* out = (float*)d_out;

    hm_main_kernel<<<NWORK + 1, THREADS>>>(fm, lms, out);
}

// round 10
// speedup vs baseline: 1.7450x; 1.4183x over previous
#include <cuda_runtime.h>

// Problem constants (fixed shapes from reference)
#define BB 4
#define NN 19
#define HH 512
#define WW 512
#define HWc (HH * WW)          // 262144
#define CC 57
#define PAIRS (BB * NN)        // 76
#define THREADS 256

#define NSTREAM (148 * 7)                    // 1036 stream CTAs (flat bce sum)
#define NDISK PAIRS                          // 76 disk CTAs
#define NWORK (NSTREAM + NDISK)              // 1112 workers (+1 watcher)
#define NV4 (BB * NN * (HWc / 4))            // 4,980,736 float4 of logits

#define RAD 40
#define BBOX 81                              // 2*RAD+1
#define BBOX2 (BBOX * BBOX)                  // 6561

// Accumulators. Zero at module load; watcher resets after consuming ->
// state identical on every graph replay.
__device__ float g_shot;                     // global sum of bce hot terms
__device__ float g_bce[PAIRS];               // per-pair: -sum_heat(l)
__device__ float g_l1x[PAIRS];
__device__ float g_l1y[PAIRS];
__device__ float g_cnt[PAIRS];
__device__ unsigned int g_count = 0;

__global__ __launch_bounds__(THREADS, 7) void hm_main_kernel(
    const float* __restrict__ fm, const float* __restrict__ lms,
    float* __restrict__ out)
{
    const int warp = threadIdx.x >> 5;
    const int lane = threadIdx.x & 31;

    // ---------------- watcher CTA: finalize ----------------
    if (blockIdx.x == NWORK) {
        const int tid = threadIdx.x;
        if (tid == 0) {
            volatile unsigned int* vc = &g_count;
            while (*vc != (unsigned int)NWORK) __nanosleep(200);
        }
        __syncthreads();
        __threadfence();   // acquire: accumulator REDs visible after count

        float t = 0.0f;
        if (tid < PAIRS) {
            const float vb = __ldcg(&g_bce[tid]);     // = -sum_heat(l)
            const float vx = __ldcg(&g_l1x[tid]);
            const float vy = __ldcg(&g_l1y[tid]);
            const float vn = __ldcg(&g_cnt[tid]);
            t = 2.0f * vb * (1.0f / (float)HWc) + (vx + vy) / vn;
        }
        #pragma unroll
        for (int o = 16; o > 0; o >>= 1)
            t += __shfl_down_sync(0xFFFFFFFFu, t, o);

        __shared__ float s[8];
        if (lane == 0) s[warp] = t;
        __syncthreads();
        if (tid == 0) {
            float sum = 0.0f;
            #pragma unroll
            for (int i = 0; i < 8; i++) sum += s[i];
            // add the global hot-term once: 2*S_hot/HW (spread over all pairs)
            sum += 2.0f * __ldcg(&g_shot) * (1.0f / (float)HWc);
            out[0] = sum / (float)PAIRS;
        }
        // reset state for the next graph replay (end state == initial state)
        if (tid < PAIRS) {
            g_bce[tid] = 0.0f; g_l1x[tid] = 0.0f;
            g_l1y[tid] = 0.0f; g_cnt[tid] = 0.0f;
        }
        if (tid == 0) { g_shot = 0.0f; g_count = 0; }
        return;
    }

    // ---------------- disk CTAs: per-pair heat-region terms ----------------
    if (blockIdx.x >= NSTREAM) {
        const int pair = blockIdx.x - NSTREAM;   // 0..75
        const int b = pair / NN;
        const int n = pair % NN;
        const float lx = lms[pair * 2 + 0];
        const float ly = lms[pair * 2 + 1];
        const int x = (int)(lx * (float)HH);
        const int y = (int)(ly * (float)WW);

        const size_t base = ((size_t)(b * CC + n)) * (size_t)HWc;
        const float* __restrict__ pL = fm + base;
        const float* __restrict__ pX = fm + base + (size_t)NN * HWc;
        const float* __restrict__ pY = fm + base + (size_t)(2 * NN) * HWc;

        float subL = 0.0f, l1x = 0.0f, l1y = 0.0f;
        int cnt = 0;

        for (int idx = threadIdx.x; idx < BBOX2; idx += THREADS) {
            const int r  = idx / BBOX;       // 0..80
            const int cc = idx - r * BBOX;   // 0..80
            const int di = r - RAD;
            const int dj = cc - RAD;
            const int gi = x + di;
            const int gj = y + dj;
            if ((unsigned)gi < HH && (unsigned)gj < WW &&
                di * di + dj * dj <= RAD * RAD) {
                const int off = gi * WW + gj;
                const float l  = __ldg(pL + off);
                const float px = __ldg(pX + off);
                const float py = __ldg(pY + off);
                subL += l;
                l1x += fabsf(px + (float)di * (1.0f / 40.0f));  // |px - (-di/40)|
                l1y += fabsf(py + (float)dj * (1.0f / 40.0f));
                cnt++;
            }
        }

        float c = (float)cnt;
        float nb = -subL;   // contribution to bce: -sum_heat(l)
        #pragma unroll
        for (int o = 16; o > 0; o >>= 1) {
            nb  += __shfl_down_sync(0xFFFFFFFFu, nb, o);
            l1x += __shfl_down_sync(0xFFFFFFFFu, l1x, o);
            l1y += __shfl_down_sync(0xFFFFFFFFu, l1y, o);
            c   += __shfl_down_sync(0xFFFFFFFFu, c, o);
        }
        __shared__ float d0[8], d1[8], d2[8], d3[8];
        if (lane == 0) { d0[warp] = nb; d1[warp] = l1x; d2[warp] = l1y; d3[warp] = c; }
        __syncthreads();
        if (threadIdx.x == 0) {
            float v0 = 0.f, v1 = 0.f, v2 = 0.f, v3 = 0.f;
            #pragma unroll
            for (int i = 0; i < 8; i++) {
                v0 += d0[i]; v1 += d1[i]; v2 += d2[i]; v3 += d3[i];
            }
            atomicAdd(&g_bce[pair], v0);
            atomicAdd(&g_l1x[pair], v1);
            atomicAdd(&g_l1y[pair], v2);
            atomicAdd(&g_cnt[pair], v3);
            __threadfence();
            atomicAdd(&g_count, 1u);
        }
        return;
    }

    // ---------------- stream CTAs: flat bce hot-term sum ----------------
    // S_hot = sum over ALL logits pixels of max(l,0) + log(1+exp(-|l|)).
    // No per-pair bookkeeping: contiguous grid-stride over 4.98M float4.
    const float4* __restrict__ pL = (const float4*)fm;

    float bce_lin = 0.0f;   // Sum of (l + |l|)  == 2*max(l,0)
    float bce_log = 0.0f;   // Sum of log(1+exp(-|l|)) via log-of-products

    const int T = NSTREAM * THREADS;         // total stream threads
    int i = blockIdx.x * THREADS + threadIdx.x;

    // main loop: 4 independent LDG.128 in flight (16 buffer regs, no spill)
    for (; i + 3 * T < NV4; i += 4 * T) {
        const float4 A = __ldcs(pL + i);
        const float4 B = __ldcs(pL + i + T);
        const float4 C = __ldcs(pL + i + 2 * T);
        const float4 D = __ldcs(pL + i + 3 * T);

        #pragma unroll
        for (int q = 0; q < 4; q++) {
            const float4 L = (q == 0) ? A : (q == 1) ? B : (q == 2) ? C : D;
            const float a0 = fabsf(L.x), a1 = fabsf(L.y);
            const float a2 = fabsf(L.z), a3 = fabsf(L.w);
            bce_lin += ((L.x + a0) + (L.y + a1)) + ((L.z + a2) + (L.w + a3));
            const float e0 = 1.0f + __expf(-a0);
            const float e1 = 1.0f + __expf(-a1);
            const float e2 = 1.0f + __expf(-a2);
            const float e3 = 1.0f + __expf(-a3);
            bce_log += __logf((e0 * e1) * (e2 * e3));
        }
    }
    // remainder
    for (; i < NV4; i += T) {
        const float4 L = __ldcs(pL + i);
        const float a0 = fabsf(L.x), a1 = fabsf(L.y);
        const float a2 = fabsf(L.z), a3 = fabsf(L.w);
        bce_lin += ((L.x + a0) + (L.y + a1)) + ((L.z + a2) + (L.w + a3));
        const float e0 = 1.0f + __expf(-a0);
        const float e1 = 1.0f + __expf(-a1);
        const float e2 = 1.0f + __expf(-a2);
        const float e3 = 1.0f + __expf(-a3);
        bce_log += __logf((e0 * e1) * (e2 * e3));
    }

    float bce = fmaf(0.5f, bce_lin, bce_log);

    #pragma unroll
    for (int o = 16; o > 0; o >>= 1)
        bce += __shfl_down_sync(0xFFFFFFFFu, bce, o);

    __shared__ float s0[8];
    if (lane == 0) s0[warp] = bce;
    __syncthreads();
    // warps 1..7 retire here; only thread0 pays the fence.

    if (threadIdx.x == 0) {
        float v0 = 0.f;
        #pragma unroll
        for (int i2 = 0; i2 < 8; i2++) v0 += s0[i2];
        atomicAdd(&g_shot, v0);        // fire-and-forget REDG, single scalar
        __threadfence();               // order data RED before the count RED
        atomicAdd(&g_count, 1u);
    }
}

extern "C" void kernel_launch(void* const* d_in, const int* in_sizes, int n_in,
                              void* d_out, int out_size)
{
    const float* fm  = (const float*)d_in[0];   // feature_maps (4,57,512,512) f32
    const float* lms = (const float*)d_in[1];   // landmarks (4,19,2) f32
    float* out = (float*)d_out;

    hm_main_kernel<<<NWORK + 1, THREADS>>>(fm, lms, out);
}